// round 16
// baseline (speedup 1.0000x reference)
#include <cuda_runtime.h>
#include <cuda_fp16.h>
#include <math.h>
#include <stdint.h>

#define B_DIM 1024
#define D_DIM 512
#define C_DIM 51332
#define C_TILES 402
#define C_PAD (C_TILES * 128)       // 51456

#define EPS_F   1e-3f
#define SCALE_F 64.0f

// ---------------- persistent device scratch (no runtime allocation) --------
__device__ __align__(256) float  g_part[4 * C_PAD];              // partial col sumsq
__device__ __align__(256) float  g_invnorm[C_PAD];
__device__ __align__(256) __half g_kf16[(size_t)D_DIM * C_PAD];  // kernel fp16 [D, C_PAD]
__device__ __align__(256) __half g_ef16[B_DIM * D_DIM];          // emb fp16 [B, D]

// ---------------------------------------------------------------------------
// Kernel 1: fp16-convert + partial column sumsq, split 4x along d for occupancy
// ---------------------------------------------------------------------------
__global__ void kprep_part_kernel(const float* __restrict__ kern) {
    int c = blockIdx.x * blockDim.x + threadIdx.x;   // blockDim = 128
    if (c >= C_PAD) return;
    const int d0 = blockIdx.y * 128;
    if (c >= C_DIM) {   // padding columns: zero-fill fp16, zero partial
        for (int d = d0; d < d0 + 128; ++d)
            g_kf16[(size_t)d * C_PAD + c] = __ushort_as_half((unsigned short)0);
        g_part[blockIdx.y * C_PAD + c] = 0.0f;
        return;
    }
    float s0 = 0.f, s1 = 0.f, s2 = 0.f, s3 = 0.f;
#pragma unroll 8
    for (int d = d0; d < d0 + 128; d += 4) {
        float v0 = kern[(size_t)(d + 0) * C_DIM + c];
        float v1 = kern[(size_t)(d + 1) * C_DIM + c];
        float v2 = kern[(size_t)(d + 2) * C_DIM + c];
        float v3 = kern[(size_t)(d + 3) * C_DIM + c];
        s0 = fmaf(v0, v0, s0);
        s1 = fmaf(v1, v1, s1);
        s2 = fmaf(v2, v2, s2);
        s3 = fmaf(v3, v3, s3);
        g_kf16[(size_t)(d + 0) * C_PAD + c] = __float2half_rn(v0);
        g_kf16[(size_t)(d + 1) * C_PAD + c] = __float2half_rn(v1);
        g_kf16[(size_t)(d + 2) * C_PAD + c] = __float2half_rn(v2);
        g_kf16[(size_t)(d + 3) * C_PAD + c] = __float2half_rn(v3);
    }
    g_part[blockIdx.y * C_PAD + c] = (s0 + s1) + (s2 + s3);
}

// ---------------------------------------------------------------------------
// Kernel 2: reduce partials -> invnorm (deterministic order)
// ---------------------------------------------------------------------------
__global__ void invnorm_kernel() {
    int c = blockIdx.x * blockDim.x + threadIdx.x;
    if (c >= C_DIM) return;
    float s = ((g_part[c] + g_part[C_PAD + c]) +
               (g_part[2 * C_PAD + c] + g_part[3 * C_PAD + c]));
    g_invnorm[c] = 1.0f / fmaxf(sqrtf(s), 1e-5f);
}

// ---------------------------------------------------------------------------
// Kernel 3: embeddings -> fp16
// ---------------------------------------------------------------------------
__global__ void ef16_kernel(const float* __restrict__ emb) {
    int i = (blockIdx.x * blockDim.x + threadIdx.x) * 4;
    if (i >= B_DIM * D_DIM) return;
    float4 v = *reinterpret_cast<const float4*>(emb + i);
    __half2 h01 = __floats2half2_rn(v.x, v.y);
    __half2 h23 = __floats2half2_rn(v.z, v.w);
    uint2 u;
    u.x = *reinterpret_cast<uint32_t*>(&h01);
    u.y = *reinterpret_cast<uint32_t*>(&h23);
    *reinterpret_cast<uint2*>(g_ef16 + i) = u;
}

// ---------------------------------------------------------------------------
// Kernel 4: fp16 mma.sync GEMM, 128x128 tile, 4 warps of 64x64, BKK=64:
// 8 mainloop stages (half the barrier/wait drains of BKK=32).
// 2-stage cp.async double buffer, dynamic smem 70KB, 2 CTAs/SM.
// ---------------------------------------------------------------------------
#define BKK 64
#define AS_STRIDE 72                 // 64 halves + 8 pad (36 words: conflict-free)
#define BS_STRIDE 136                // 128 halves + 8 pad (68 words: conflict-free)
#define A_TILE (128 * AS_STRIDE)     // halves
#define B_TILE (BKK * BS_STRIDE)     // halves
#define NSTAGE (D_DIM / BKK)         // 8
#define SMEM_BYTES ((2 * A_TILE + 2 * B_TILE) * 2)

__device__ __forceinline__ unsigned sptr(const void* p) {
    return (unsigned)__cvta_generic_to_shared(p);
}
__device__ __forceinline__ void cp16(unsigned dst, const void* src) {
    asm volatile("cp.async.cg.shared.global [%0], [%1], 16;" :: "r"(dst), "l"(src));
}
__device__ __forceinline__ void ldsm_x4(uint32_t* r, unsigned addr) {
    asm volatile("ldmatrix.sync.aligned.m8n8.x4.shared.b16 {%0,%1,%2,%3}, [%4];"
                 : "=r"(r[0]), "=r"(r[1]), "=r"(r[2]), "=r"(r[3]) : "r"(addr));
}
__device__ __forceinline__ void ldsm_x4t(uint32_t* r, unsigned addr) {
    asm volatile("ldmatrix.sync.aligned.m8n8.x4.trans.shared.b16 {%0,%1,%2,%3}, [%4];"
                 : "=r"(r[0]), "=r"(r[1]), "=r"(r[2]), "=r"(r[3]) : "r"(addr));
}
__device__ __forceinline__ void mma16816(float* c, const uint32_t* a, const uint32_t* b) {
    asm volatile("mma.sync.aligned.m16n8k16.row.col.f32.f16.f16.f32 "
                 "{%0,%1,%2,%3}, {%4,%5,%6,%7}, {%8,%9}, {%0,%1,%2,%3};"
                 : "+f"(c[0]), "+f"(c[1]), "+f"(c[2]), "+f"(c[3])
                 : "r"(a[0]), "r"(a[1]), "r"(a[2]), "r"(a[3]), "r"(b[0]), "r"(b[1]));
}

__global__ __launch_bounds__(128, 2)
void gemm_f16_kernel(float* __restrict__ out)
{
    extern __shared__ __half smem[];
    __half* sA = smem;                  // 2 * A_TILE
    __half* sB = smem + 2 * A_TILE;     // 2 * B_TILE

    const int tid  = threadIdx.x;
    const int lane = tid & 31;
    const int warp = tid >> 5;       // 0..3
    const int wm   = warp >> 1;      // 0..1 (64-row slab)
    const int wn   = warp & 1;       // 0..1 (64-col slab)
    const int rowBase = blockIdx.x * 128;   // row tile fastest -> B slab L2 reuse
    const int colBase = blockIdx.y * 128;

    float acc[4][8][4];
#pragma unroll
    for (int i = 0; i < 4; ++i)
#pragma unroll
        for (int j = 0; j < 8; ++j)
#pragma unroll
            for (int q = 0; q < 4; ++q) acc[i][j][q] = 0.0f;

    // byte-exact loader: cp16 = 16B = 8 halves, offsets in halves are ch*8
    auto load_stage = [&](int ks, int buf) {
        const int k0 = ks * BKK;
        // A: 128 rows x 64 half = 1024 x 16B chunks, 8 per thread
#pragma unroll
        for (int r = 0; r < 8; ++r) {
            int t   = tid + r * 128;
            int row = t >> 3;            // 0..127
            int ch  = t & 7;             // 0..7
            cp16(sptr(sA + buf * A_TILE + row * AS_STRIDE + ch * 8),
                 g_ef16 + (size_t)(rowBase + row) * D_DIM + k0 + ch * 8);
        }
        // B: 64 rows x 128 half = 1024 x 16B chunks, 8 per thread
#pragma unroll
        for (int r = 0; r < 8; ++r) {
            int t   = tid + r * 128;
            int row = t >> 4;            // 0..63
            int ch  = t & 15;            // 0..15
            cp16(sptr(sB + buf * B_TILE + row * BS_STRIDE + ch * 8),
                 g_kf16 + (size_t)(k0 + row) * C_PAD + colBase + ch * 8);
        }
    };

    auto compute_stage = [&](int buf) {
        const __half* A  = sA + buf * A_TILE;
        const __half* Bt = sB + buf * B_TILE;
#pragma unroll
        for (int h = 0; h < 4; ++h) {            // 4 k16 halves per K=64 stage
            const int k16 = h * 16;
            uint32_t af[4][4], bf[8][2];
#pragma unroll
            for (int mt = 0; mt < 4; ++mt) {
                int row = wm * 64 + mt * 16 + (lane & 15);
                int kc  = k16 + (lane >> 4) * 8;
                ldsm_x4(af[mt], sptr(A + row * AS_STRIDE + kc));
            }
            {
                int r = lane & 7;
                int g = lane >> 3;
                int krow = k16 + ((g & 1) << 3) + r;
                int cofs = (g >> 1) << 3;
#pragma unroll
                for (int nt2 = 0; nt2 < 4; ++nt2) {
                    int nc = wn * 64 + nt2 * 16 + cofs;
                    uint32_t rr4[4];
                    ldsm_x4t(rr4, sptr(Bt + krow * BS_STRIDE + nc));
                    bf[nt2 * 2 + 0][0] = rr4[0];
                    bf[nt2 * 2 + 0][1] = rr4[1];
                    bf[nt2 * 2 + 1][0] = rr4[2];
                    bf[nt2 * 2 + 1][1] = rr4[3];
                }
            }
#pragma unroll
            for (int mt = 0; mt < 4; ++mt)
#pragma unroll
                for (int nt = 0; nt < 8; ++nt)
                    mma16816(acc[mt][nt], af[mt], bf[nt]);
        }
    };

    // ---- proven 2-stage pipeline: 8 stages of K=64 ----
    load_stage(0, 0);
    asm volatile("cp.async.commit_group;");
    for (int ks = 0; ks < NSTAGE; ++ks) {
        if (ks + 1 < NSTAGE) {
            load_stage(ks + 1, (ks + 1) & 1);
            asm volatile("cp.async.commit_group;");
            asm volatile("cp.async.wait_group 1;");
        } else {
            asm volatile("cp.async.wait_group 0;");
        }
        __syncthreads();
        compute_stage(ks & 1);
        __syncthreads();
    }

    // epilogue: * invnorm[c], clip, * scale
#pragma unroll
    for (int mt = 0; mt < 4; ++mt) {
#pragma unroll
        for (int nt = 0; nt < 8; ++nt) {
            int col = colBase + wn * 64 + nt * 8 + (lane & 3) * 2;
            if (col >= C_DIM) continue;
            float2 inv = *reinterpret_cast<const float2*>(g_invnorm + col);
#pragma unroll
            for (int rr = 0; rr < 2; ++rr) {
                int row = rowBase + wm * 64 + mt * 16 + (lane >> 2) + rr * 8;
                float2 v;
                v.x = fminf(fmaxf(acc[mt][nt][rr * 2 + 0] * inv.x, -1.0f + EPS_F), 1.0f - EPS_F) * SCALE_F;
                v.y = fminf(fmaxf(acc[mt][nt][rr * 2 + 1] * inv.y, -1.0f + EPS_F), 1.0f - EPS_F) * SCALE_F;
                *reinterpret_cast<float2*>(out + (size_t)row * C_DIM + col) = v;
            }
        }
    }
}

// ---------------------------------------------------------------------------
// Kernel 5: patch label entries IN-PLACE from the GEMM output.
// ---------------------------------------------------------------------------
__global__ void patch_label_kernel(const float* __restrict__ norms,
                                   const int*   __restrict__ label,
                                   float* __restrict__ out)
{
    int b = blockIdx.x * blockDim.x + threadIdx.x;
    if (b >= B_DIM) return;

    int col = label[b];
    size_t idx = (size_t)b * C_DIM + col;
    float cosv = out[idx] * (1.0f / SCALE_F);   // already clipped

    float sn = fminf(fmaxf(norms[b], 1e-3f), 100.0f);
    float ms = sn / (100.0f + EPS_F) * 0.333f;        // BATCH_MEAN = 0
    ms = fminf(fmaxf(ms, -1.0f), 1.0f);

    float theta = acosf(cosv) + 0.5f * ms;            // M = 0.5
    const float PI_F = 3.14159265358979323846f;
    theta = fminf(fmaxf(theta, EPS_F), PI_F - EPS_F);
    float cm = cosf(theta) - (0.5f - 0.5f * ms);      // HEAD_B = 0.5
    out[idx] = cm * SCALE_F;
}

// ---------------------------------------------------------------------------
extern "C" void kernel_launch(void* const* d_in, const int* in_sizes, int n_in,
                              void* d_out, int out_size)
{
    const float* emb   = (const float*)d_in[0];  // [1024, 512]
    const float* norms = (const float*)d_in[1];  // [1024, 1]
    const float* kern  = (const float*)d_in[2];  // [512, 51332]
    const int*   label = (const int*)  d_in[3];  // [1024]
    float*       out   = (float*)d_out;          // [1024, 51332]

    cudaFuncSetAttribute(gemm_f16_kernel,
                         cudaFuncAttributeMaxDynamicSharedMemorySize, SMEM_BYTES);

    dim3 pgrid(C_PAD / 128, 4);
    kprep_part_kernel<<<pgrid, 128>>>(kern);
    invnorm_kernel<<<(C_DIM + 255) / 256, 256>>>();

    ef16_kernel<<<(B_DIM * D_DIM / 4 + 255) / 256, 256>>>(emb);

    dim3 ggrid(B_DIM / 128, C_TILES);   // row tile fastest -> B slab L2 reuse
    gemm_f16_kernel<<<ggrid, 128, SMEM_BYTES>>>(out);

    patch_label_kernel<<<(B_DIM + 255) / 256, 256>>>(norms, label, out);
}

// round 17
// speedup vs baseline: 1.0177x; 1.0177x over previous
#include <cuda_runtime.h>
#include <cuda_fp16.h>
#include <math.h>
#include <stdint.h>

#define B_DIM 1024
#define D_DIM 512
#define C_DIM 51332
#define C_TILES 402
#define C_PAD (C_TILES * 128)       // 51456

#define EPS_F   1e-3f
#define SCALE_F 64.0f

// ---------------- persistent device scratch (no runtime allocation) --------
__device__ __align__(256) float  g_part[4 * C_PAD];              // partial col sumsq
__device__ __align__(256) float  g_invnorm[C_PAD];
__device__ __align__(256) __half g_kf16[(size_t)D_DIM * C_PAD];  // kernel fp16 [D, C_PAD]
__device__ __align__(256) __half g_ef16[B_DIM * D_DIM];          // emb fp16 [B, D]

// ---------------------------------------------------------------------------
// Kernel 1: fp16-convert + partial column sumsq, split 4x along d for occupancy
// ---------------------------------------------------------------------------
__global__ void kprep_part_kernel(const float* __restrict__ kern) {
    int c = blockIdx.x * blockDim.x + threadIdx.x;   // blockDim = 128
    if (c >= C_PAD) return;
    const int d0 = blockIdx.y * 128;
    if (c >= C_DIM) {   // padding columns: zero-fill fp16, zero partial
        for (int d = d0; d < d0 + 128; ++d)
            g_kf16[(size_t)d * C_PAD + c] = __ushort_as_half((unsigned short)0);
        g_part[blockIdx.y * C_PAD + c] = 0.0f;
        return;
    }
    float s0 = 0.f, s1 = 0.f, s2 = 0.f, s3 = 0.f;
#pragma unroll 8
    for (int d = d0; d < d0 + 128; d += 4) {
        float v0 = kern[(size_t)(d + 0) * C_DIM + c];
        float v1 = kern[(size_t)(d + 1) * C_DIM + c];
        float v2 = kern[(size_t)(d + 2) * C_DIM + c];
        float v3 = kern[(size_t)(d + 3) * C_DIM + c];
        s0 = fmaf(v0, v0, s0);
        s1 = fmaf(v1, v1, s1);
        s2 = fmaf(v2, v2, s2);
        s3 = fmaf(v3, v3, s3);
        g_kf16[(size_t)(d + 0) * C_PAD + c] = __float2half_rn(v0);
        g_kf16[(size_t)(d + 1) * C_PAD + c] = __float2half_rn(v1);
        g_kf16[(size_t)(d + 2) * C_PAD + c] = __float2half_rn(v2);
        g_kf16[(size_t)(d + 3) * C_PAD + c] = __float2half_rn(v3);
    }
    g_part[blockIdx.y * C_PAD + c] = (s0 + s1) + (s2 + s3);
}

// ---------------------------------------------------------------------------
// Kernel 2: reduce partials -> invnorm (deterministic order)
// ---------------------------------------------------------------------------
__global__ void invnorm_kernel() {
    int c = blockIdx.x * blockDim.x + threadIdx.x;
    if (c >= C_DIM) return;
    float s = ((g_part[c] + g_part[C_PAD + c]) +
               (g_part[2 * C_PAD + c] + g_part[3 * C_PAD + c]));
    g_invnorm[c] = 1.0f / fmaxf(sqrtf(s), 1e-5f);
}

// ---------------------------------------------------------------------------
// Kernel 3: embeddings -> fp16
// ---------------------------------------------------------------------------
__global__ void ef16_kernel(const float* __restrict__ emb) {
    int i = (blockIdx.x * blockDim.x + threadIdx.x) * 4;
    if (i >= B_DIM * D_DIM) return;
    float4 v = *reinterpret_cast<const float4*>(emb + i);
    __half2 h01 = __floats2half2_rn(v.x, v.y);
    __half2 h23 = __floats2half2_rn(v.z, v.w);
    uint2 u;
    u.x = *reinterpret_cast<uint32_t*>(&h01);
    u.y = *reinterpret_cast<uint32_t*>(&h23);
    *reinterpret_cast<uint2*>(g_ef16 + i) = u;
}

// ---------------------------------------------------------------------------
// Kernel 4: fp16 mma.sync GEMM, 128x128 tile, 4 warps of 64x64, BKK=32.
// NEW: per-stage, ALL 16 ldsm (both k16 halves) issued up front, then one
// 64-MMA dependence-free run -> more smem MLP, fewer issue stalls.
// ---------------------------------------------------------------------------
#define BKK 32
#define AS_STRIDE 40
#define BS_STRIDE 136
#define A_TILE (128 * AS_STRIDE)
#define B_TILE (BKK * BS_STRIDE)

__device__ __forceinline__ unsigned sptr(const void* p) {
    return (unsigned)__cvta_generic_to_shared(p);
}
__device__ __forceinline__ void cp16(unsigned dst, const void* src) {
    asm volatile("cp.async.cg.shared.global [%0], [%1], 16;" :: "r"(dst), "l"(src));
}
__device__ __forceinline__ void ldsm_x4(uint32_t* r, unsigned addr) {
    asm volatile("ldmatrix.sync.aligned.m8n8.x4.shared.b16 {%0,%1,%2,%3}, [%4];"
                 : "=r"(r[0]), "=r"(r[1]), "=r"(r[2]), "=r"(r[3]) : "r"(addr));
}
__device__ __forceinline__ void ldsm_x4t(uint32_t* r, unsigned addr) {
    asm volatile("ldmatrix.sync.aligned.m8n8.x4.trans.shared.b16 {%0,%1,%2,%3}, [%4];"
                 : "=r"(r[0]), "=r"(r[1]), "=r"(r[2]), "=r"(r[3]) : "r"(addr));
}
__device__ __forceinline__ void mma16816(float* c, const uint32_t* a, const uint32_t* b) {
    asm volatile("mma.sync.aligned.m16n8k16.row.col.f32.f16.f16.f32 "
                 "{%0,%1,%2,%3}, {%4,%5,%6,%7}, {%8,%9}, {%0,%1,%2,%3};"
                 : "+f"(c[0]), "+f"(c[1]), "+f"(c[2]), "+f"(c[3])
                 : "r"(a[0]), "r"(a[1]), "r"(a[2]), "r"(a[3]), "r"(b[0]), "r"(b[1]));
}

__global__ __launch_bounds__(128, 2)
void gemm_f16_kernel(float* __restrict__ out)
{
    __shared__ __half sA[2 * A_TILE];
    __shared__ __half sB[2 * B_TILE];

    const int tid  = threadIdx.x;
    const int lane = tid & 31;
    const int warp = tid >> 5;       // 0..3
    const int wm   = warp >> 1;      // 0..1 (64-row slab)
    const int wn   = warp & 1;       // 0..1 (64-col slab)
    const int rowBase = blockIdx.x * 128;   // row tile fastest -> B slab L2 reuse
    const int colBase = blockIdx.y * 128;

    float acc[4][8][4];
#pragma unroll
    for (int i = 0; i < 4; ++i)
#pragma unroll
        for (int j = 0; j < 8; ++j)
#pragma unroll
            for (int q = 0; q < 4; ++q) acc[i][j][q] = 0.0f;

    // ---- precomputed per-thread ldsm base addresses (bytes) ----
    unsigned a_base[4], b_base[4];
    {
        int kc = (lane >> 4) * 8;
#pragma unroll
        for (int mt = 0; mt < 4; ++mt) {
            int row = wm * 64 + mt * 16 + (lane & 15);
            a_base[mt] = sptr(sA) + 2u * (row * AS_STRIDE + kc);
        }
        int r = lane & 7;
        int g = lane >> 3;
        int krow = ((g & 1) << 3) + r;
        int cofs = (g >> 1) << 3;
#pragma unroll
        for (int nt2 = 0; nt2 < 4; ++nt2) {
            int nc = wn * 64 + nt2 * 16 + cofs;
            b_base[nt2] = sptr(sB) + 2u * (krow * BS_STRIDE + nc);
        }
    }

    auto load_stage = [&](int ks, int buf) {
        const int k0 = ks * BKK;
#pragma unroll
        for (int r = 0; r < 4; ++r) {
            int t   = tid + r * 128;
            int row = t >> 2;
            int ch  = t & 3;
            cp16(sptr(sA + buf * A_TILE + row * AS_STRIDE + ch * 8),
                 g_ef16 + (size_t)(rowBase + row) * D_DIM + k0 + ch * 8);
        }
#pragma unroll
        for (int r = 0; r < 4; ++r) {
            int t   = tid + r * 128;
            int row = t >> 4;
            int ch  = t & 15;
            cp16(sptr(sB + buf * B_TILE + row * BS_STRIDE + ch * 8),
                 g_kf16 + (size_t)(k0 + row) * C_PAD + colBase + ch * 8);
        }
    };

    auto compute_stage = [&](int buf) {
        const unsigned abuf = buf * (unsigned)(A_TILE * 2);
        const unsigned bbuf = buf * (unsigned)(B_TILE * 2);
        uint32_t af[2][4][4], bf[2][8][2];
        // ---- all 16 ldsm up front (both k16 halves) ----
#pragma unroll
        for (int h = 0; h < 2; ++h) {
            const unsigned ak = abuf + h * 32u;                       // +16 halves
            const unsigned bk = bbuf + h * (unsigned)(16 * BS_STRIDE * 2);
#pragma unroll
            for (int mt = 0; mt < 4; ++mt)
                ldsm_x4(af[h][mt], a_base[mt] + ak);
#pragma unroll
            for (int nt2 = 0; nt2 < 4; ++nt2) {
                uint32_t rr4[4];
                ldsm_x4t(rr4, b_base[nt2] + bk);
                bf[h][nt2 * 2 + 0][0] = rr4[0];
                bf[h][nt2 * 2 + 0][1] = rr4[1];
                bf[h][nt2 * 2 + 1][0] = rr4[2];
                bf[h][nt2 * 2 + 1][1] = rr4[3];
            }
        }
        // ---- one 64-MMA dependence-free run ----
#pragma unroll
        for (int h = 0; h < 2; ++h)
#pragma unroll
            for (int mt = 0; mt < 4; ++mt)
#pragma unroll
                for (int nt = 0; nt < 8; ++nt)
                    mma16816(acc[mt][nt], af[h][mt], bf[h][nt]);
    };

    // ---- proven 2-stage pipeline: 16 stages of K=32 ----
    load_stage(0, 0);
    asm volatile("cp.async.commit_group;");
    for (int ks = 0; ks < 16; ++ks) {
        if (ks + 1 < 16) {
            load_stage(ks + 1, (ks + 1) & 1);
            asm volatile("cp.async.commit_group;");
            asm volatile("cp.async.wait_group 1;");
        } else {
            asm volatile("cp.async.wait_group 0;");
        }
        __syncthreads();
        compute_stage(ks & 1);
        __syncthreads();
    }

    // epilogue: * invnorm[c], clip, * scale
#pragma unroll
    for (int mt = 0; mt < 4; ++mt) {
#pragma unroll
        for (int nt = 0; nt < 8; ++nt) {
            int col = colBase + wn * 64 + nt * 8 + (lane & 3) * 2;
            if (col >= C_DIM) continue;
            float2 inv = *reinterpret_cast<const float2*>(g_invnorm + col);
#pragma unroll
            for (int rr = 0; rr < 2; ++rr) {
                int row = rowBase + wm * 64 + mt * 16 + (lane >> 2) + rr * 8;
                float2 v;
                v.x = fminf(fmaxf(acc[mt][nt][rr * 2 + 0] * inv.x, -1.0f + EPS_F), 1.0f - EPS_F) * SCALE_F;
                v.y = fminf(fmaxf(acc[mt][nt][rr * 2 + 1] * inv.y, -1.0f + EPS_F), 1.0f - EPS_F) * SCALE_F;
                *reinterpret_cast<float2*>(out + (size_t)row * C_DIM + col) = v;
            }
        }
    }
}

// ---------------------------------------------------------------------------
// Kernel 5: patch label entries IN-PLACE from the GEMM output.
// ---------------------------------------------------------------------------
__global__ void patch_label_kernel(const float* __restrict__ norms,
                                   const int*   __restrict__ label,
                                   float* __restrict__ out)
{
    int b = blockIdx.x * blockDim.x + threadIdx.x;
    if (b >= B_DIM) return;

    int col = label[b];
    size_t idx = (size_t)b * C_DIM + col;
    float cosv = out[idx] * (1.0f / SCALE_F);   // already clipped

    float sn = fminf(fmaxf(norms[b], 1e-3f), 100.0f);
    float ms = sn / (100.0f + EPS_F) * 0.333f;        // BATCH_MEAN = 0
    ms = fminf(fmaxf(ms, -1.0f), 1.0f);

    float theta = acosf(cosv) + 0.5f * ms;            // M = 0.5
    const float PI_F = 3.14159265358979323846f;
    theta = fminf(fmaxf(theta, EPS_F), PI_F - EPS_F);
    float cm = cosf(theta) - (0.5f - 0.5f * ms);      // HEAD_B = 0.5
    out[idx] = cm * SCALE_F;
}

// ---------------------------------------------------------------------------
extern "C" void kernel_launch(void* const* d_in, const int* in_sizes, int n_in,
                              void* d_out, int out_size)
{
    const float* emb   = (const float*)d_in[0];  // [1024, 512]
    const float* norms = (const float*)d_in[1];  // [1024, 1]
    const float* kern  = (const float*)d_in[2];  // [512, 51332]
    const int*   label = (const int*)  d_in[3];  // [1024]
    float*       out   = (float*)d_out;          // [1024, 51332]

    dim3 pgrid(C_PAD / 128, 4);
    kprep_part_kernel<<<pgrid, 128>>>(kern);
    invnorm_kernel<<<(C_DIM + 255) / 256, 256>>>();

    ef16_kernel<<<(B_DIM * D_DIM / 4 + 255) / 256, 256>>>(emb);

    dim3 ggrid(B_DIM / 128, C_TILES);   // row tile fastest -> B slab L2 reuse
    gemm_f16_kernel<<<ggrid, 128>>>(out);

    patch_label_kernel<<<(B_DIM + 255) / 256, 256>>>(norms, label, out);
}